// round 1
// baseline (speedup 1.0000x reference)
#include <cuda_runtime.h>

// Problem constants (fixed by reference setup_inputs):
//   adj: (B=2, N=2048, N=2048, F=16) float32
//   filter_size f = 8, stride = 4, n = 2048
//   starts = 0,4,...,2040  -> 511 starts
//   off-diagonal positions in 8x8 window: 56 of them
//   out: (B, 511, 56*16) float32
//
// Off-diag position pos in [0,56): local = pos + 1 + pos/8  (skips multiples of 9)
//   ii = local / 8, jj = local % 8
// Input element index (floats):
//   b*N*N*F + (start+ii)*N*F + (start+jj)*F + f
// = b*N*N*F + start*(N+1)*F + (ii*N + jj)*F + f
//
// One thread per float4 (16 B). Output is written fully contiguously
// (out float4 index == global thread index). Input loads are 16B each,
// grouping into 64B per position and near-contiguous ~512B per window row.

namespace {
constexpr int B        = 2;
constexpr int N        = 2048;
constexpr int F        = 16;
constexpr int STRIDE   = 4;
constexpr int NSTARTS  = 511;   // (2048 - 8)/4 + 1
constexpr int NPOS     = 56;    // 8*8 - 8
constexpr int VEC_PER_POS = F / 4;                      // 4 float4 per position
constexpr long TOTAL_VEC  = (long)B * NSTARTS * NPOS * VEC_PER_POS; // 228,928
}

__global__ void __launch_bounds__(256)
sparse_diag_unfold_kernel(const float4* __restrict__ adj, float4* __restrict__ out)
{
    int idx = blockIdx.x * blockDim.x + threadIdx.x;   // float4 index into out
    if (idx >= (int)TOTAL_VEC) return;

    int v   = idx & 3;          // which float4 of the 16-float feature vector
    int t   = idx >> 2;         // linear (b, s, pos)
    int pos = t % NPOS;
    int bs  = t / NPOS;
    int s   = bs % NSTARTS;
    int b   = bs / NSTARTS;

    int local = pos + 1 + (pos >> 3);   // skip diagonal entries (local % 9 == 0)
    int ii = local >> 3;
    int jj = local & 7;

    // base element offset in floats; always a multiple of F=16 (so /4 is exact)
    long base_f = ((long)b * N * N
                 + (long)(s * STRIDE) * (N + 1)
                 + (long)ii * N + jj) * F;

    out[idx] = adj[(base_f >> 2) + v];
}

extern "C" void kernel_launch(void* const* d_in, const int* in_sizes, int n_in,
                              void* d_out, int out_size)
{
    const float4* adj = (const float4*)d_in[0];
    float4* out = (float4*)d_out;

    const int threads = 256;
    const int blocks  = (int)((TOTAL_VEC + threads - 1) / threads);  // 895
    sparse_diag_unfold_kernel<<<blocks, threads>>>(adj, out);
}